// round 11
// baseline (speedup 1.0000x reference)
#include <cuda_runtime.h>

#define LEAK 0.2f
constexpr int B_  = 2;
constexpr int C_  = 16;
constexpr int VOL = 96 * 96 * 96;
constexpr int PLN = 96 * 96;
constexpr int DVF = 48;

typedef unsigned long long pk_t;

// Scratch (device globals per harness rules).
__device__ float g_warped[(size_t)B_ * C_ * VOL];  // warped src; later fsum
__device__ float g_corr[(size_t)B_ * 27 * VOL];    // cost volume
__device__ float g_facc[(size_t)B_ * C_ * VOL];    // conv1 out (f)

__device__ __forceinline__ float lrelu(float v) { return v > 0.f ? v : LEAK * v; }

__device__ __forceinline__ pk_t pack2(float lo, float hi) {
    pk_t r; asm("mov.b64 %0, {%1,%2};" : "=l"(r) : "f"(lo), "f"(hi)); return r;
}
__device__ __forceinline__ void unpack2(pk_t p, float& lo, float& hi) {
    asm("mov.b64 {%0,%1}, %2;" : "=f"(lo), "=f"(hi) : "l"(p));
}
__device__ __forceinline__ pk_t ffma2(pk_t a, pk_t b, pk_t c) {
    pk_t d; asm("fma.rn.f32x2 %0, %1, %2, %3;" : "=l"(d) : "l"(a), "l"(b), "l"(c));
    return d;
}

// ---------------------------------------------------------------------------
// K1: trilinear upsample of dvf (48^3 -> 96^3, align_corners) + warp source
// ---------------------------------------------------------------------------
__global__ void warp_kernel(const float* __restrict__ src,
                            const float* __restrict__ dvf)
{
    int idx = blockIdx.x * blockDim.x + threadIdx.x;
    if (idx >= B_ * VOL) return;
    int b = idx / VOL;
    int r = idx - b * VOL;
    int z = r / PLN;
    int y = (r / 96) % 96;
    int x = r % 96;

    const float sc = 47.0f / 95.0f;
    float pz = z * sc, py = y * sc, px = x * sc;
    int z0 = (int)pz, y0 = (int)py, x0 = (int)px;
    int z1 = min(z0 + 1, DVF - 1), y1 = min(y0 + 1, DVF - 1), x1 = min(x0 + 1, DVF - 1);
    float wz = pz - (float)z0, wy = py - (float)y0, wx = px - (float)x0;

    const float* dv = dvf + (size_t)b * 3 * DVF * DVF * DVF;
    float flow[3];
#pragma unroll
    for (int cc = 0; cc < 3; cc++) {
        const float* p = dv + (size_t)cc * DVF * DVF * DVF;
        float v000 = __ldg(p + (z0 * 48 + y0) * 48 + x0);
        float v001 = __ldg(p + (z0 * 48 + y0) * 48 + x1);
        float v010 = __ldg(p + (z0 * 48 + y1) * 48 + x0);
        float v011 = __ldg(p + (z0 * 48 + y1) * 48 + x1);
        float v100 = __ldg(p + (z1 * 48 + y0) * 48 + x0);
        float v101 = __ldg(p + (z1 * 48 + y0) * 48 + x1);
        float v110 = __ldg(p + (z1 * 48 + y1) * 48 + x0);
        float v111 = __ldg(p + (z1 * 48 + y1) * 48 + x1);
        float v00 = v000 * (1.f - wx) + v001 * wx;
        float v01 = v010 * (1.f - wx) + v011 * wx;
        float v10 = v100 * (1.f - wx) + v101 * wx;
        float v11 = v110 * (1.f - wx) + v111 * wx;
        float v0 = v00 * (1.f - wy) + v01 * wy;
        float v1 = v10 * (1.f - wy) + v11 * wy;
        flow[cc] = v0 * (1.f - wz) + v1 * wz;
    }

    float zc = (float)z + flow[0];
    float yc = (float)y + flow[1];
    float xc = (float)x + flow[2];
    float zf = floorf(zc), yf = floorf(yc), xf = floorf(xc);
    float fz = zc - zf, fy = yc - yf, fx = xc - xf;
    int iz0 = (int)zf, iy0 = (int)yf, ix0 = (int)xf;

    int   zi[2] = { iz0, iz0 + 1 };
    int   yi[2] = { iy0, iy0 + 1 };
    int   xi[2] = { ix0, ix0 + 1 };
    float wzv[2] = { 1.f - fz, fz };
    float wyv[2] = { 1.f - fy, fy };
    float wxv[2] = { 1.f - fx, fx };

    int   idx8[8];
    float w8[8];
    int j = 0;
#pragma unroll
    for (int a = 0; a < 2; a++)
#pragma unroll
        for (int bb = 0; bb < 2; bb++)
#pragma unroll
            for (int c2 = 0; c2 < 2; c2++) {
                int zz = zi[a], yy = yi[bb], xx = xi[c2];
                bool valid = (zz >= 0 && zz < 96 && yy >= 0 && yy < 96 &&
                              xx >= 0 && xx < 96);
                int zcl = min(max(zz, 0), 95);
                int ycl = min(max(yy, 0), 95);
                int xcl = min(max(xx, 0), 95);
                idx8[j] = (zcl * 96 + ycl) * 96 + xcl;
                w8[j] = valid ? (wzv[a] * wyv[bb] * wxv[c2]) : 0.f;
                j++;
            }

    const float* sb = src + (size_t)b * C_ * VOL;
    float* ob = g_warped + (size_t)b * C_ * VOL + r;
#pragma unroll
    for (int c = 0; c < C_; c++) {
        const float* sp = sb + (size_t)c * VOL;
        float v = 0.f;
#pragma unroll
        for (int k = 0; k < 8; k++) v = fmaf(w8[k], __ldg(sp + idx8[k]), v);
        ob[(size_t)c * VOL] = v;
    }
}

// ---------------------------------------------------------------------------
// K2: 27-shift cost volume, f32x2 packed, 2 x per thread
// ---------------------------------------------------------------------------
__global__ void __launch_bounds__(256, 2) corrp_kernel(const float* __restrict__ tgt)
{
    constexpr int ZCC = 12, NZCC = 96 / ZCC;
    int bz = blockIdx.z;
    int zc = bz % NZCC; bz /= NZCC;
    int b = bz;
    int tx = threadIdx.x, ty = threadIdx.y;
    int gx = blockIdx.x * 32 + tx * 2;
    int y  = blockIdx.y * 16 + ty;
    int zs = zc * ZCC;

    const float* wb = g_warped + (size_t)b * C_ * VOL;
    const float* tb = tgt + (size_t)b * C_ * VOL;

    for (int z = zs; z < zs + ZCC; z++) {
        pk_t acc[27];
#pragma unroll
        for (int s = 0; s < 27; s++) acc[s] = 0ull;

#pragma unroll 1
        for (int ch = 0; ch < C_; ch++) {
            pk_t t2 = *(const pk_t*)(tb + (size_t)ch * VOL + (size_t)z * PLN + y * 96 + gx);
#pragma unroll
            for (int dz = 0; dz < 3; dz++) {
                int zz = z + dz - 1;
                bool vz = (zz >= 0 && zz <= 95);
#pragma unroll
                for (int dy = 0; dy < 3; dy++) {
                    int yy = y + dy - 1;
                    bool vr = vz && (yy >= 0 && yy <= 95);
                    const float* pr = wb + (size_t)ch * VOL + (size_t)zz * PLN + yy * 96 + gx;
                    float m0 = 0.f, m1 = 0.f, vl = 0.f, vrv = 0.f;
                    if (vr) {
                        float2 m = __ldg((const float2*)pr);
                        m0 = m.x; m1 = m.y;
                        if (gx > 0)  vl  = __ldg(pr - 1);
                        if (gx < 94) vrv = __ldg(pr + 2);
                    }
                    pk_t pL = pack2(vl, m0);
                    pk_t pC = pack2(m0, m1);
                    pk_t pR = pack2(m1, vrv);
                    int s = dz * 9 + dy * 3;
                    acc[s]     = ffma2(t2, pL, acc[s]);
                    acc[s + 1] = ffma2(t2, pC, acc[s + 1]);
                    acc[s + 2] = ffma2(t2, pR, acc[s + 2]);
                }
            }
        }

        float* op = g_corr + (size_t)b * 27 * VOL + (size_t)z * PLN + y * 96 + gx;
#pragma unroll
        for (int s = 0; s < 27; s++) {
            float lo, hi;
            unpack2(acc[s], lo, hi);
            lo = lrelu(lo * 0.0625f);
            hi = lrelu(hi * 0.0625f);
            *(float2*)(op + (size_t)s * VOL) = make_float2(lo, hi);
        }
    }
}

// ---------------------------------------------------------------------------
// Batch-packed 3x3x3 conv: f32x2 lanes = (batch0, batch1). COG=2 couts,
// 4 x-outputs/thread. Per row per batch: 1 LDG.128 + 2 edge LDG.32.
// Weights broadcast from smem: [ci][tap9][kz3][co2] duplicated (w,w).
// Block (8,16) -> 32x16 xy tile, z-ring over ZCc chunk.
// ---------------------------------------------------------------------------
template<int CIN0, int CIN1, int CIN2, int NCG, int COUT_STORE, int ZCc, bool RES>
__global__ void __launch_bounds__(128, 4) convb4_kernel(
    const float* __restrict__ in0, const float* __restrict__ in1,
    const float* __restrict__ in2,
    const float* __restrict__ w, const float* __restrict__ bias,
    float* __restrict__ out, const float* __restrict__ res)
{
    constexpr int CTOT = CIN0 + CIN1 + CIN2;
    constexpr int NZCc = 96 / ZCc;
    extern __shared__ char smraw[];
    pk_t* swgt = (pk_t*)smraw;   // [ci][tap9][kz3][co2] duplicated

    int bz = blockIdx.z;
    int zc = bz % NZCc;
    int cg = bz / NZCc;
    int co0 = cg * 2;

    int tid = threadIdx.y * 8 + threadIdx.x;
    for (int i = tid; i < CTOT * 54; i += 128) {
        int co = i & 1;
        int kz = (i >> 1) % 3;
        int t  = (i / 6) % 9;
        int ci = i / 54;
        float wv = (co0 + co < COUT_STORE)
            ? __ldg(w + ((size_t)(co0 + co) * CTOT + ci) * 27 + kz * 9 + t) : 0.f;
        swgt[i] = pack2(wv, wv);
    }
    __syncthreads();

    int x = blockIdx.x * 32 + threadIdx.x * 4;   // outputs x..x+3
    int y = blockIdx.y * 16 + threadIdx.y;
    int zs = zc * ZCc;

    bool vxm = (x >= 1), vxp = (x <= 91);

    const float* base0 = in0;
    const float* base1 = in1;
    const float* base2 = in2;

    // acc layout: [j*2 + co], j = x-offset 0..3, lanes = (b0, b1)
    pk_t a0[8], a1[8], a2[8];
#pragma unroll
    for (int i = 0; i < 8; i++) { a0[i] = 0ull; a1[i] = 0ull; a2[i] = 0ull; }

#define SEG_LOOP(BASE, CINSEG, CIOFF, AP, AC, AN)                              \
    _Pragma("unroll 1")                                                        \
    for (int ci = 0; ci < (CINSEG); ci++) {                                    \
        const float* q0 = (BASE) + (size_t)ci * VOL + (size_t)z * PLN +        \
                          y * 96 + x;                                          \
        const float* q1 = q0 + (size_t)(CINSEG) * VOL;                         \
        const pk_t* wci = swgt + (size_t)((CIOFF) + ci) * 54;                  \
        _Pragma("unroll")                                                      \
        for (int dy = 0; dy < 3; dy++) {                                       \
            int yy = y + dy - 1;                                               \
            bool vy = (yy >= 0 && yy <= 95);                                   \
            const float* r0 = q0 + (dy - 1) * 96;                              \
            const float* r1 = q1 + (dy - 1) * 96;                              \
            float4 A0 = make_float4(0.f, 0.f, 0.f, 0.f);                       \
            float4 A1 = make_float4(0.f, 0.f, 0.f, 0.f);                       \
            float l0 = 0.f, l1 = 0.f, h0 = 0.f, h1 = 0.f;                      \
            if (vy) {                                                          \
                A0 = __ldg((const float4*)r0);                                 \
                A1 = __ldg((const float4*)r1);                                 \
                if (vxm) { l0 = __ldg(r0 - 1); l1 = __ldg(r1 - 1); }           \
                if (vxp) { h0 = __ldg(r0 + 4); h1 = __ldg(r1 + 4); }           \
            }                                                                  \
            pk_t P[6];                                                         \
            P[0] = pack2(l0, l1);                                              \
            P[1] = pack2(A0.x, A1.x);                                          \
            P[2] = pack2(A0.y, A1.y);                                          \
            P[3] = pack2(A0.z, A1.z);                                          \
            P[4] = pack2(A0.w, A1.w);                                          \
            P[5] = pack2(h0, h1);                                              \
            const pk_t* wrow = wci + dy * 18;                                  \
            _Pragma("unroll")                                                  \
            for (int kx = 0; kx < 3; kx++) {                                   \
                const pk_t* wk = wrow + kx * 6;                                \
                ulonglong2 w0 = *(const ulonglong2*)(wk);      /* kz0 */       \
                ulonglong2 w1 = *(const ulonglong2*)(wk + 2);  /* kz1 */       \
                ulonglong2 w2 = *(const ulonglong2*)(wk + 4);  /* kz2 */       \
                _Pragma("unroll")                                              \
                for (int j = 0; j < 4; j++) {                                  \
                    pk_t Pv = P[j + kx];                                       \
                    AN[j * 2]     = ffma2(Pv, w0.x, AN[j * 2]);                \
                    AN[j * 2 + 1] = ffma2(Pv, w0.y, AN[j * 2 + 1]);            \
                    AC[j * 2]     = ffma2(Pv, w1.x, AC[j * 2]);                \
                    AC[j * 2 + 1] = ffma2(Pv, w1.y, AC[j * 2 + 1]);            \
                    AP[j * 2]     = ffma2(Pv, w2.x, AP[j * 2]);                \
                    AP[j * 2 + 1] = ffma2(Pv, w2.y, AP[j * 2 + 1]);            \
                }                                                              \
            }                                                                  \
        }                                                                      \
    }

#define CONV_STEP(ZP, AP, AC, AN)                                              \
    {                                                                          \
        int z = (ZP);                                                          \
        if (z >= 0 && z <= 95 && z <= zs + ZCc) {                              \
            SEG_LOOP(base0, CIN0, 0, AP, AC, AN);                              \
            if (CIN1 > 0) { SEG_LOOP(base1, CIN1, CIN0, AP, AC, AN); }         \
            if (CIN2 > 0) { SEG_LOOP(base2, CIN2, CIN0 + CIN1, AP, AC, AN); }  \
        }                                                                      \
        int zo = z - 1;                                                        \
        if (zo >= zs && zo < zs + ZCc) {                                       \
            size_t bstr = (size_t)COUT_STORE * VOL;                            \
            _Pragma("unroll")                                                  \
            for (int co = 0; co < 2; co++) {                                   \
                if (co0 + co < COUT_STORE) {                                   \
                    size_t off = (size_t)(co0 + co) * VOL +                    \
                                 (size_t)zo * PLN + y * 96 + x;                \
                    float bv = __ldg(bias + co0 + co);                         \
                    float o0[4], o1[4];                                        \
                    _Pragma("unroll")                                          \
                    for (int j = 0; j < 4; j++) {                              \
                        unpack2(AP[j * 2 + co], o0[j], o1[j]);                 \
                        o0[j] = lrelu(o0[j] + bv);                             \
                        o1[j] = lrelu(o1[j] + bv);                             \
                    }                                                          \
                    if (RES) {                                                 \
                        float4 r0v = __ldg((const float4*)(res + off));        \
                        float4 r1v = __ldg((const float4*)(res + off + bstr)); \
                        o0[0] += r0v.x; o0[1] += r0v.y;                        \
                        o0[2] += r0v.z; o0[3] += r0v.w;                        \
                        o1[0] += r1v.x; o1[1] += r1v.y;                        \
                        o1[2] += r1v.z; o1[3] += r1v.w;                        \
                    }                                                          \
                    *(float4*)(out + off) =                                    \
                        make_float4(o0[0], o0[1], o0[2], o0[3]);               \
                    *(float4*)(out + off + bstr) =                             \
                        make_float4(o1[0], o1[1], o1[2], o1[3]);               \
                }                                                              \
            }                                                                  \
        }                                                                      \
        _Pragma("unroll")                                                      \
        for (int i = 0; i < 8; i++) AP[i] = 0ull;                              \
    }

    for (int zb = zs - 1; zb <= zs + ZCc; zb += 3) {
        CONV_STEP(zb,     a0, a1, a2);
        CONV_STEP(zb + 1, a1, a2, a0);
        CONV_STEP(zb + 2, a2, a0, a1);
    }
#undef CONV_STEP
#undef SEG_LOOP
}

// ---------------------------------------------------------------------------
extern "C" void kernel_launch(void* const* d_in, const int* in_sizes, int n_in,
                              void* d_out, int out_size)
{
    const float* src = (const float*)d_in[0];
    const float* tgt = (const float*)d_in[1];
    const float* dvf = (const float*)d_in[2];
    const float* w1  = (const float*)d_in[3];
    const float* b1  = (const float*)d_in[4];
    const float* w2  = (const float*)d_in[5];
    const float* b2  = (const float*)d_in[6];
    const float* w3  = (const float*)d_in[7];
    const float* b3  = (const float*)d_in[8];
    float* out = (float*)d_out;

    float* warped = nullptr;
    float* corr   = nullptr;
    float* facc   = nullptr;
    cudaGetSymbolAddress((void**)&warped, g_warped);
    cudaGetSymbolAddress((void**)&corr, g_corr);
    cudaGetSymbolAddress((void**)&facc, g_facc);

    const int sm1 = 59 * 54 * (int)sizeof(pk_t);   // 25488
    const int sm2 = 16 * 54 * (int)sizeof(pk_t);   //  6912

    cudaFuncSetAttribute((const void*)&convb4_kernel<16, 27, 16, 8, 16, 12, false>,
                         cudaFuncAttributeMaxDynamicSharedMemorySize, sm1);
    cudaFuncSetAttribute((const void*)&convb4_kernel<16, 0, 0, 8, 16, 12, true>,
                         cudaFuncAttributeMaxDynamicSharedMemorySize, sm2);
    cudaFuncSetAttribute((const void*)&convb4_kernel<16, 0, 0, 2, 3, 6, false>,
                         cudaFuncAttributeMaxDynamicSharedMemorySize, sm2);

    int nvox = B_ * VOL;
    warp_kernel<<<(nvox + 255) / 256, 256>>>(src, dvf);

    dim3 cblk(16, 16);
    dim3 cgrd(3, 6, 8 * B_);
    corrp_kernel<<<cgrd, cblk>>>(tgt);

    dim3 blk(8, 16);
    dim3 g1(3, 6, 8 * 8);     // ZC=12 (NZC=8) x NCG=8 -> 1152 blocks
    dim3 g3(3, 6, 16 * 2);    // ZC=6 (NZC=16) x NCG=2 -> 576 blocks

    // conv1 fused over its 3 input segments (src, corr, tgt): 59ch -> 16ch, lrelu
    convb4_kernel<16, 27, 16, 8, 16, 12, false>
        <<<g1, blk, sm1>>>(src, corr, tgt, w1, b1, facc, nullptr);
    // conv2 + residual: fsum = f + lrelu(conv(f))
    convb4_kernel<16, 0, 0, 8, 16, 12, true>
        <<<g1, blk, sm2>>>(facc, nullptr, nullptr, w2, b2, warped, facc);
    // conv3: 16 -> 3
    convb4_kernel<16, 0, 0, 2, 3, 6, false>
        <<<g3, blk, sm2>>>(warped, nullptr, nullptr, w3, b3, out, nullptr);
}

// round 12
// speedup vs baseline: 1.8402x; 1.8402x over previous
#include <cuda_runtime.h>

#define LEAK 0.2f
constexpr int B_  = 2;
constexpr int C_  = 16;
constexpr int VOL = 96 * 96 * 96;
constexpr int PLN = 96 * 96;
constexpr int DVF = 48;

typedef unsigned long long pk_t;

// Scratch (device globals per harness rules).
__device__ float g_warped[(size_t)B_ * C_ * VOL];  // warped src; later fsum
__device__ float g_corr[(size_t)B_ * 27 * VOL];    // cost volume
__device__ float g_facc[(size_t)B_ * C_ * VOL];    // conv1 out (f)

__device__ __forceinline__ float lrelu(float v) { return v > 0.f ? v : LEAK * v; }

__device__ __forceinline__ pk_t pack2(float lo, float hi) {
    pk_t r; asm("mov.b64 %0, {%1,%2};" : "=l"(r) : "f"(lo), "f"(hi)); return r;
}
__device__ __forceinline__ void unpack2(pk_t p, float& lo, float& hi) {
    asm("mov.b64 {%0,%1}, %2;" : "=f"(lo), "=f"(hi) : "l"(p));
}
__device__ __forceinline__ pk_t ffma2(pk_t a, pk_t b, pk_t c) {
    pk_t d; asm("fma.rn.f32x2 %0, %1, %2, %3;" : "=l"(d) : "l"(a), "l"(b), "l"(c));
    return d;
}

// ---------------------------------------------------------------------------
// K1: trilinear upsample of dvf (48^3 -> 96^3, align_corners) + warp source
// ---------------------------------------------------------------------------
__global__ void warp_kernel(const float* __restrict__ src,
                            const float* __restrict__ dvf)
{
    int idx = blockIdx.x * blockDim.x + threadIdx.x;
    if (idx >= B_ * VOL) return;
    int b = idx / VOL;
    int r = idx - b * VOL;
    int z = r / PLN;
    int y = (r / 96) % 96;
    int x = r % 96;

    const float sc = 47.0f / 95.0f;
    float pz = z * sc, py = y * sc, px = x * sc;
    int z0 = (int)pz, y0 = (int)py, x0 = (int)px;
    int z1 = min(z0 + 1, DVF - 1), y1 = min(y0 + 1, DVF - 1), x1 = min(x0 + 1, DVF - 1);
    float wz = pz - (float)z0, wy = py - (float)y0, wx = px - (float)x0;

    const float* dv = dvf + (size_t)b * 3 * DVF * DVF * DVF;
    float flow[3];
#pragma unroll
    for (int cc = 0; cc < 3; cc++) {
        const float* p = dv + (size_t)cc * DVF * DVF * DVF;
        float v000 = __ldg(p + (z0 * 48 + y0) * 48 + x0);
        float v001 = __ldg(p + (z0 * 48 + y0) * 48 + x1);
        float v010 = __ldg(p + (z0 * 48 + y1) * 48 + x0);
        float v011 = __ldg(p + (z0 * 48 + y1) * 48 + x1);
        float v100 = __ldg(p + (z1 * 48 + y0) * 48 + x0);
        float v101 = __ldg(p + (z1 * 48 + y0) * 48 + x1);
        float v110 = __ldg(p + (z1 * 48 + y1) * 48 + x0);
        float v111 = __ldg(p + (z1 * 48 + y1) * 48 + x1);
        float v00 = v000 * (1.f - wx) + v001 * wx;
        float v01 = v010 * (1.f - wx) + v011 * wx;
        float v10 = v100 * (1.f - wx) + v101 * wx;
        float v11 = v110 * (1.f - wx) + v111 * wx;
        float v0 = v00 * (1.f - wy) + v01 * wy;
        float v1 = v10 * (1.f - wy) + v11 * wy;
        flow[cc] = v0 * (1.f - wz) + v1 * wz;
    }

    float zc = (float)z + flow[0];
    float yc = (float)y + flow[1];
    float xc = (float)x + flow[2];
    float zf = floorf(zc), yf = floorf(yc), xf = floorf(xc);
    float fz = zc - zf, fy = yc - yf, fx = xc - xf;
    int iz0 = (int)zf, iy0 = (int)yf, ix0 = (int)xf;

    int   zi[2] = { iz0, iz0 + 1 };
    int   yi[2] = { iy0, iy0 + 1 };
    int   xi[2] = { ix0, ix0 + 1 };
    float wzv[2] = { 1.f - fz, fz };
    float wyv[2] = { 1.f - fy, fy };
    float wxv[2] = { 1.f - fx, fx };

    int   idx8[8];
    float w8[8];
    int j = 0;
#pragma unroll
    for (int a = 0; a < 2; a++)
#pragma unroll
        for (int bb = 0; bb < 2; bb++)
#pragma unroll
            for (int c2 = 0; c2 < 2; c2++) {
                int zz = zi[a], yy = yi[bb], xx = xi[c2];
                bool valid = (zz >= 0 && zz < 96 && yy >= 0 && yy < 96 &&
                              xx >= 0 && xx < 96);
                int zcl = min(max(zz, 0), 95);
                int ycl = min(max(yy, 0), 95);
                int xcl = min(max(xx, 0), 95);
                idx8[j] = (zcl * 96 + ycl) * 96 + xcl;
                w8[j] = valid ? (wzv[a] * wyv[bb] * wxv[c2]) : 0.f;
                j++;
            }

    const float* sb = src + (size_t)b * C_ * VOL;
    float* ob = g_warped + (size_t)b * C_ * VOL + r;
#pragma unroll
    for (int c = 0; c < C_; c++) {
        const float* sp = sb + (size_t)c * VOL;
        float v = 0.f;
#pragma unroll
        for (int k = 0; k < 8; k++) v = fmaf(w8[k], __ldg(sp + idx8[k]), v);
        ob[(size_t)c * VOL] = v;
    }
}

// ---------------------------------------------------------------------------
// K2: 27-shift cost volume, f32x2 packed, 2 x per thread
// ---------------------------------------------------------------------------
__global__ void __launch_bounds__(256, 2) corrp_kernel(const float* __restrict__ tgt)
{
    constexpr int ZCC = 12, NZCC = 96 / ZCC;
    int bz = blockIdx.z;
    int zc = bz % NZCC; bz /= NZCC;
    int b = bz;
    int tx = threadIdx.x, ty = threadIdx.y;
    int gx = blockIdx.x * 32 + tx * 2;
    int y  = blockIdx.y * 16 + ty;
    int zs = zc * ZCC;

    const float* wb = g_warped + (size_t)b * C_ * VOL;
    const float* tb = tgt + (size_t)b * C_ * VOL;

    for (int z = zs; z < zs + ZCC; z++) {
        pk_t acc[27];
#pragma unroll
        for (int s = 0; s < 27; s++) acc[s] = 0ull;

#pragma unroll 1
        for (int ch = 0; ch < C_; ch++) {
            pk_t t2 = *(const pk_t*)(tb + (size_t)ch * VOL + (size_t)z * PLN + y * 96 + gx);
#pragma unroll
            for (int dz = 0; dz < 3; dz++) {
                int zz = z + dz - 1;
                bool vz = (zz >= 0 && zz <= 95);
#pragma unroll
                for (int dy = 0; dy < 3; dy++) {
                    int yy = y + dy - 1;
                    bool vr = vz && (yy >= 0 && yy <= 95);
                    const float* pr = wb + (size_t)ch * VOL + (size_t)zz * PLN + yy * 96 + gx;
                    float m0 = 0.f, m1 = 0.f, vl = 0.f, vrv = 0.f;
                    if (vr) {
                        float2 m = __ldg((const float2*)pr);
                        m0 = m.x; m1 = m.y;
                        if (gx > 0)  vl  = __ldg(pr - 1);
                        if (gx < 94) vrv = __ldg(pr + 2);
                    }
                    pk_t pL = pack2(vl, m0);
                    pk_t pC = pack2(m0, m1);
                    pk_t pR = pack2(m1, vrv);
                    int s = dz * 9 + dy * 3;
                    acc[s]     = ffma2(t2, pL, acc[s]);
                    acc[s + 1] = ffma2(t2, pC, acc[s + 1]);
                    acc[s + 2] = ffma2(t2, pR, acc[s + 2]);
                }
            }
        }

        float* op = g_corr + (size_t)b * 27 * VOL + (size_t)z * PLN + y * 96 + gx;
#pragma unroll
        for (int s = 0; s < 27; s++) {
            float lo, hi;
            unpack2(acc[s], lo, hi);
            lo = lrelu(lo * 0.0625f);
            hi = lrelu(hi * 0.0625f);
            *(float2*)(op + (size_t)s * VOL) = make_float2(lo, hi);
        }
    }
}

// ---------------------------------------------------------------------------
// Packed 3x3x3 conv, z-ring, XPT=4 (2 packed pairs), duplicated weights in smem.
// Up to 3 input-channel segments (fused conv1). Always inits from bias.
// Block: (8,32) threads -> 32x32 xy tile, ZC z-chunk, COG couts.
// (R4 structure — best measured — with deeper z-chunks for less halo waste.)
// ---------------------------------------------------------------------------
template<int CIN0, int CIN1, int CIN2, int COUT_TOT, int COG, int COUT_STORE,
         int ZCc, bool RES>
__global__ void __launch_bounds__(256, 2) convp_kernel(
    const float* __restrict__ in0, const float* __restrict__ in1,
    const float* __restrict__ in2,
    const float* __restrict__ w, const float* __restrict__ bias,
    float* __restrict__ out, const float* __restrict__ res)
{
    constexpr int CTOT = CIN0 + CIN1 + CIN2;
    constexpr int NCG  = (COUT_TOT + COG - 1) / COG;
    constexpr int NZCc = 96 / ZCc;
    extern __shared__ char smraw[];
    pk_t* swgt = (pk_t*)smraw;   // [ci][t9][kz3][co] duplicated (w,w)

    int bz = blockIdx.z;
    int zc = bz % NZCc; bz /= NZCc;
    int cg = bz % NCG;  bz /= NCG;
    int b  = bz;
    int co0 = cg * COG;

    int tid = threadIdx.y * 8 + threadIdx.x;
    for (int i = tid; i < CTOT * 27 * COG; i += 256) {
        int co = i % COG;
        int r  = i / COG;
        int kz = r % 3;
        int t  = (r / 3) % 9;
        int ci = r / 27;
        int cog = co0 + co;
        float wv = (cog < COUT_STORE)
            ? __ldg(w + ((size_t)cog * CTOT + ci) * 27 + kz * 9 + t) : 0.f;
        swgt[i] = pack2(wv, wv);
    }
    __syncthreads();

    int gx = blockIdx.x * 32 + threadIdx.x * 4;
    int y  = blockIdx.y * 32 + threadIdx.y;
    int zs = zc * ZCc;

    const float* base0 = in0 + (size_t)b * CIN0 * VOL;
    const float* base1 = (CIN1 > 0) ? in1 + (size_t)b * CIN1 * VOL : nullptr;
    const float* base2 = (CIN2 > 0) ? in2 + (size_t)b * CIN2 * VOL : nullptr;

    pk_t bpk[COG];
#pragma unroll
    for (int co = 0; co < COG; co++) {
        float bv = (co0 + co < COUT_STORE) ? __ldg(bias + co0 + co) : 0.f;
        bpk[co] = pack2(bv, bv);
    }

    pk_t a0[2 * COG], a1[2 * COG], a2[2 * COG];
#pragma unroll
    for (int i = 0; i < 2 * COG; i++) { a0[i] = 0ull; a1[i] = 0ull; a2[i] = 0ull; }

    // Process one ci-segment's plane rows into AN/AC/AP (kz=0/1/2).
#define SEG_LOOP(BASE, CINSEG, CIOFF, AP, AC, AN)                              \
    _Pragma("unroll 1")                                                        \
    for (int ci = 0; ci < (CINSEG); ci++) {                                    \
        const float* p = (BASE) + ((size_t)ci) * VOL + (size_t)z * PLN +       \
                         y * 96 + gx;                                          \
        const pk_t* wci = swgt + (size_t)((CIOFF) + ci) * 27 * COG;            \
        _Pragma("unroll")                                                      \
        for (int dy = 0; dy < 3; dy++) {                                       \
            int yy = y + dy - 1;                                               \
            bool vy = (yy >= 0 && yy <= 95);                                   \
            const float* pr = p + (dy - 1) * 96;                               \
            float4 A = make_float4(0.f, 0.f, 0.f, 0.f);                        \
            float vl = 0.f, vr = 0.f;                                          \
            if (vy) {                                                          \
                A = __ldg((const float4*)pr);                                  \
                if (gx > 0)  vl = __ldg(pr - 1);                               \
                if (gx < 92) vr = __ldg(pr + 4);                               \
            }                                                                  \
            pk_t e0 = pack2(A.x, A.y), e1 = pack2(A.z, A.w);                   \
            pk_t s0 = pack2(vl, A.x);                                          \
            pk_t s1 = pack2(A.y, A.z);                                         \
            pk_t s2 = pack2(A.w, vr);                                          \
            _Pragma("unroll")                                                  \
            for (int kx = 0; kx < 3; kx++) {                                   \
                pk_t P0 = (kx == 0) ? s0 : (kx == 1) ? e0 : s1;                \
                pk_t P1 = (kx == 0) ? s1 : (kx == 1) ? e1 : s2;                \
                const pk_t* wt = wci + ((dy * 3 + kx) * 3) * COG;              \
                _Pragma("unroll")                                              \
                for (int co = 0; co < COG; co++) {                             \
                    pk_t wv = wt[co];                                          \
                    AN[co]       = ffma2(P0, wv, AN[co]);                      \
                    AN[COG + co] = ffma2(P1, wv, AN[COG + co]);                \
                }                                                              \
                _Pragma("unroll")                                              \
                for (int co = 0; co < COG; co++) {                             \
                    pk_t wv = wt[COG + co];                                    \
                    AC[co]       = ffma2(P0, wv, AC[co]);                      \
                    AC[COG + co] = ffma2(P1, wv, AC[COG + co]);                \
                }                                                              \
                _Pragma("unroll")                                              \
                for (int co = 0; co < COG; co++) {                             \
                    pk_t wv = wt[2 * COG + co];                                \
                    AP[co]       = ffma2(P0, wv, AP[co]);                      \
                    AP[COG + co] = ffma2(P1, wv, AP[COG + co]);                \
                }                                                              \
            }                                                                  \
        }                                                                      \
    }

#define CONV_STEP(ZP, AP, AC, AN)                                              \
    {                                                                          \
        int z = (ZP);                                                          \
        if (z >= 0 && z <= 95 && z <= zs + ZCc) {                              \
            SEG_LOOP(base0, CIN0, 0, AP, AC, AN);                              \
            if (CIN1 > 0) { SEG_LOOP(base1, CIN1, CIN0, AP, AC, AN); }         \
            if (CIN2 > 0) { SEG_LOOP(base2, CIN2, CIN0 + CIN1, AP, AC, AN); }  \
        }                                                                      \
        int zo = z - 1;                                                        \
        if (zo >= zs && zo < zs + ZCc) {                                       \
            _Pragma("unroll")                                                  \
            for (int co = 0; co < COG; co++) {                                 \
                if (co0 + co < COUT_STORE) {                                   \
                    size_t off = ((size_t)(b * COUT_STORE + co0 + co)) * VOL + \
                                 (size_t)zo * PLN + y * 96 + gx;               \
                    float o0, o1, o2, o3, blo, bhi;                            \
                    unpack2(bpk[co], blo, bhi);                                \
                    unpack2(AP[co], o0, o1);                                   \
                    unpack2(AP[COG + co], o2, o3);                             \
                    o0 = lrelu(o0 + blo); o1 = lrelu(o1 + bhi);                \
                    o2 = lrelu(o2 + blo); o3 = lrelu(o3 + bhi);                \
                    if (RES) {                                                 \
                        float4 r4 = __ldg((const float4*)(res + off));         \
                        o0 += r4.x; o1 += r4.y; o2 += r4.z; o3 += r4.w;        \
                    }                                                          \
                    *(float4*)(out + off) = make_float4(o0, o1, o2, o3);       \
                }                                                              \
            }                                                                  \
        }                                                                      \
        _Pragma("unroll")                                                      \
        for (int i = 0; i < 2 * COG; i++) AP[i] = 0ull;                        \
    }

    for (int zb = zs - 1; zb <= zs + ZCc; zb += 3) {
        CONV_STEP(zb,     a0, a1, a2);
        CONV_STEP(zb + 1, a1, a2, a0);
        CONV_STEP(zb + 2, a2, a0, a1);
    }
#undef CONV_STEP
#undef SEG_LOOP
}

// ---------------------------------------------------------------------------
extern "C" void kernel_launch(void* const* d_in, const int* in_sizes, int n_in,
                              void* d_out, int out_size)
{
    const float* src = (const float*)d_in[0];
    const float* tgt = (const float*)d_in[1];
    const float* dvf = (const float*)d_in[2];
    const float* w1  = (const float*)d_in[3];
    const float* b1  = (const float*)d_in[4];
    const float* w2  = (const float*)d_in[5];
    const float* b2  = (const float*)d_in[6];
    const float* w3  = (const float*)d_in[7];
    const float* b3  = (const float*)d_in[8];
    float* out = (float*)d_out;

    float* warped = nullptr;
    float* corr   = nullptr;
    float* facc   = nullptr;
    cudaGetSymbolAddress((void**)&warped, g_warped);
    cudaGetSymbolAddress((void**)&corr, g_corr);
    cudaGetSymbolAddress((void**)&facc, g_facc);

    const int sm1 = 59 * 27 * 4 * (int)sizeof(pk_t);   // 50976
    const int sm2 = 16 * 27 * 4 * (int)sizeof(pk_t);   // 13824
    const int sm3 = 16 * 27 * 3 * (int)sizeof(pk_t);   // 10368

    cudaFuncSetAttribute((const void*)&convp_kernel<16, 27, 16, 16, 4, 16, 24, false>,
                         cudaFuncAttributeMaxDynamicSharedMemorySize, sm1);
    cudaFuncSetAttribute((const void*)&convp_kernel<16, 0, 0, 16, 4, 16, 24, true>,
                         cudaFuncAttributeMaxDynamicSharedMemorySize, sm2);
    cudaFuncSetAttribute((const void*)&convp_kernel<16, 0, 0, 3, 3, 3, 6, false>,
                         cudaFuncAttributeMaxDynamicSharedMemorySize, sm3);

    int nvox = B_ * VOL;
    warp_kernel<<<(nvox + 255) / 256, 256>>>(src, dvf);

    dim3 cblk(16, 16);
    dim3 cgrd(3, 6, 8 * B_);
    corrp_kernel<<<cgrd, cblk>>>(tgt);

    dim3 blk(8, 32);
    dim3 g1(3, 3, 4 * 4 * B_);    // ZC=24 (NZC=4) x NCG=4 x B -> 288 blocks (1 wave)
    dim3 g3(3, 3, 16 * 1 * B_);   // ZC=6  (NZC=16) x NCG=1 x B -> 288 blocks

    // conv1 fused over its 3 input segments (src, corr, tgt): 59ch -> 16ch, lrelu
    convp_kernel<16, 27, 16, 16, 4, 16, 24, false>
        <<<g1, blk, sm1>>>(src, corr, tgt, w1, b1, facc, nullptr);
    // conv2 + residual: fsum = f + lrelu(conv(f))
    convp_kernel<16, 0, 0, 16, 4, 16, 24, true>
        <<<g1, blk, sm2>>>(facc, nullptr, nullptr, w2, b2, warped, facc);
    // conv3: 16 -> 3
    convp_kernel<16, 0, 0, 3, 3, 3, 6, false>
        <<<g3, blk, sm3>>>(warped, nullptr, nullptr, w3, b3, out, nullptr);
}

// round 13
// speedup vs baseline: 1.8706x; 1.0166x over previous
#include <cuda_runtime.h>

#define LEAK 0.2f
constexpr int B_  = 2;
constexpr int C_  = 16;
constexpr int VOL = 96 * 96 * 96;
constexpr int PLN = 96 * 96;
constexpr int DVF = 48;

typedef unsigned long long pk_t;

// Scratch (device globals per harness rules).
__device__ float g_warped[(size_t)B_ * C_ * VOL];  // warped src; later fsum
__device__ float g_corr[(size_t)B_ * 27 * VOL];    // cost volume
__device__ float g_facc[(size_t)B_ * C_ * VOL];    // conv1 out (f)

__device__ __forceinline__ float lrelu(float v) { return v > 0.f ? v : LEAK * v; }

__device__ __forceinline__ pk_t pack2(float lo, float hi) {
    pk_t r; asm("mov.b64 %0, {%1,%2};" : "=l"(r) : "f"(lo), "f"(hi)); return r;
}
__device__ __forceinline__ void unpack2(pk_t p, float& lo, float& hi) {
    asm("mov.b64 {%0,%1}, %2;" : "=f"(lo), "=f"(hi) : "l"(p));
}
__device__ __forceinline__ pk_t ffma2(pk_t a, pk_t b, pk_t c) {
    pk_t d; asm("fma.rn.f32x2 %0, %1, %2, %3;" : "=l"(d) : "l"(a), "l"(b), "l"(c));
    return d;
}

// ---------------------------------------------------------------------------
// K1: trilinear upsample of dvf (48^3 -> 96^3, align_corners) + warp source
// ---------------------------------------------------------------------------
__global__ void warp_kernel(const float* __restrict__ src,
                            const float* __restrict__ dvf)
{
    int idx = blockIdx.x * blockDim.x + threadIdx.x;
    if (idx >= B_ * VOL) return;
    int b = idx / VOL;
    int r = idx - b * VOL;
    int z = r / PLN;
    int y = (r / 96) % 96;
    int x = r % 96;

    const float sc = 47.0f / 95.0f;
    float pz = z * sc, py = y * sc, px = x * sc;
    int z0 = (int)pz, y0 = (int)py, x0 = (int)px;
    int z1 = min(z0 + 1, DVF - 1), y1 = min(y0 + 1, DVF - 1), x1 = min(x0 + 1, DVF - 1);
    float wz = pz - (float)z0, wy = py - (float)y0, wx = px - (float)x0;

    const float* dv = dvf + (size_t)b * 3 * DVF * DVF * DVF;
    float flow[3];
#pragma unroll
    for (int cc = 0; cc < 3; cc++) {
        const float* p = dv + (size_t)cc * DVF * DVF * DVF;
        float v000 = __ldg(p + (z0 * 48 + y0) * 48 + x0);
        float v001 = __ldg(p + (z0 * 48 + y0) * 48 + x1);
        float v010 = __ldg(p + (z0 * 48 + y1) * 48 + x0);
        float v011 = __ldg(p + (z0 * 48 + y1) * 48 + x1);
        float v100 = __ldg(p + (z1 * 48 + y0) * 48 + x0);
        float v101 = __ldg(p + (z1 * 48 + y0) * 48 + x1);
        float v110 = __ldg(p + (z1 * 48 + y1) * 48 + x0);
        float v111 = __ldg(p + (z1 * 48 + y1) * 48 + x1);
        float v00 = v000 * (1.f - wx) + v001 * wx;
        float v01 = v010 * (1.f - wx) + v011 * wx;
        float v10 = v100 * (1.f - wx) + v101 * wx;
        float v11 = v110 * (1.f - wx) + v111 * wx;
        float v0 = v00 * (1.f - wy) + v01 * wy;
        float v1 = v10 * (1.f - wy) + v11 * wy;
        flow[cc] = v0 * (1.f - wz) + v1 * wz;
    }

    float zc = (float)z + flow[0];
    float yc = (float)y + flow[1];
    float xc = (float)x + flow[2];
    float zf = floorf(zc), yf = floorf(yc), xf = floorf(xc);
    float fz = zc - zf, fy = yc - yf, fx = xc - xf;
    int iz0 = (int)zf, iy0 = (int)yf, ix0 = (int)xf;

    int   zi[2] = { iz0, iz0 + 1 };
    int   yi[2] = { iy0, iy0 + 1 };
    int   xi[2] = { ix0, ix0 + 1 };
    float wzv[2] = { 1.f - fz, fz };
    float wyv[2] = { 1.f - fy, fy };
    float wxv[2] = { 1.f - fx, fx };

    int   idx8[8];
    float w8[8];
    int j = 0;
#pragma unroll
    for (int a = 0; a < 2; a++)
#pragma unroll
        for (int bb = 0; bb < 2; bb++)
#pragma unroll
            for (int c2 = 0; c2 < 2; c2++) {
                int zz = zi[a], yy = yi[bb], xx = xi[c2];
                bool valid = (zz >= 0 && zz < 96 && yy >= 0 && yy < 96 &&
                              xx >= 0 && xx < 96);
                int zcl = min(max(zz, 0), 95);
                int ycl = min(max(yy, 0), 95);
                int xcl = min(max(xx, 0), 95);
                idx8[j] = (zcl * 96 + ycl) * 96 + xcl;
                w8[j] = valid ? (wzv[a] * wyv[bb] * wxv[c2]) : 0.f;
                j++;
            }

    const float* sb = src + (size_t)b * C_ * VOL;
    float* ob = g_warped + (size_t)b * C_ * VOL + r;
#pragma unroll
    for (int c = 0; c < C_; c++) {
        const float* sp = sb + (size_t)c * VOL;
        float v = 0.f;
#pragma unroll
        for (int k = 0; k < 8; k++) v = fmaf(w8[k], __ldg(sp + idx8[k]), v);
        ob[(size_t)c * VOL] = v;
    }
}

// ---------------------------------------------------------------------------
// K2: 27-shift cost volume, f32x2 packed, 2 x per thread
// ---------------------------------------------------------------------------
__global__ void __launch_bounds__(256, 2) corrp_kernel(const float* __restrict__ tgt)
{
    constexpr int ZCC = 12, NZCC = 96 / ZCC;
    int bz = blockIdx.z;
    int zc = bz % NZCC; bz /= NZCC;
    int b = bz;
    int tx = threadIdx.x, ty = threadIdx.y;
    int gx = blockIdx.x * 32 + tx * 2;
    int y  = blockIdx.y * 16 + ty;
    int zs = zc * ZCC;

    const float* wb = g_warped + (size_t)b * C_ * VOL;
    const float* tb = tgt + (size_t)b * C_ * VOL;

    for (int z = zs; z < zs + ZCC; z++) {
        pk_t acc[27];
#pragma unroll
        for (int s = 0; s < 27; s++) acc[s] = 0ull;

#pragma unroll 1
        for (int ch = 0; ch < C_; ch++) {
            pk_t t2 = *(const pk_t*)(tb + (size_t)ch * VOL + (size_t)z * PLN + y * 96 + gx);
#pragma unroll
            for (int dz = 0; dz < 3; dz++) {
                int zz = z + dz - 1;
                bool vz = (zz >= 0 && zz <= 95);
#pragma unroll
                for (int dy = 0; dy < 3; dy++) {
                    int yy = y + dy - 1;
                    bool vr = vz && (yy >= 0 && yy <= 95);
                    const float* pr = wb + (size_t)ch * VOL + (size_t)zz * PLN + yy * 96 + gx;
                    float m0 = 0.f, m1 = 0.f, vl = 0.f, vrv = 0.f;
                    if (vr) {
                        float2 m = __ldg((const float2*)pr);
                        m0 = m.x; m1 = m.y;
                        if (gx > 0)  vl  = __ldg(pr - 1);
                        if (gx < 94) vrv = __ldg(pr + 2);
                    }
                    pk_t pL = pack2(vl, m0);
                    pk_t pC = pack2(m0, m1);
                    pk_t pR = pack2(m1, vrv);
                    int s = dz * 9 + dy * 3;
                    acc[s]     = ffma2(t2, pL, acc[s]);
                    acc[s + 1] = ffma2(t2, pC, acc[s + 1]);
                    acc[s + 2] = ffma2(t2, pR, acc[s + 2]);
                }
            }
        }

        float* op = g_corr + (size_t)b * 27 * VOL + (size_t)z * PLN + y * 96 + gx;
#pragma unroll
        for (int s = 0; s < 27; s++) {
            float lo, hi;
            unpack2(acc[s], lo, hi);
            lo = lrelu(lo * 0.0625f);
            hi = lrelu(hi * 0.0625f);
            *(float2*)(op + (size_t)s * VOL) = make_float2(lo, hi);
        }
    }
}

// ---------------------------------------------------------------------------
// Packed 3x3x3 conv, z-ring, XPT=4 (2 packed pairs), duplicated weights in smem.
// Weights fetched via LDS.128 (ulonglong2): layout [ci][tap9][kz3][co4] makes
// each kz-group of COG=4 pk_t a contiguous 32B, 16B-aligned run.
// Block: (8,32) threads -> 32x32 xy tile, ZC z-chunk, COG couts.
// ---------------------------------------------------------------------------
template<int CIN0, int CIN1, int CIN2, int COUT_TOT, int COG, int COUT_STORE,
         int ZCc, bool RES>
__global__ void __launch_bounds__(256, 2) convp_kernel(
    const float* __restrict__ in0, const float* __restrict__ in1,
    const float* __restrict__ in2,
    const float* __restrict__ w, const float* __restrict__ bias,
    float* __restrict__ out, const float* __restrict__ res)
{
    constexpr int CTOT = CIN0 + CIN1 + CIN2;
    constexpr int NCG  = (COUT_TOT + COG - 1) / COG;
    constexpr int NZCc = 96 / ZCc;
    constexpr int COGH = COG / 2;   // pairs of couts (COG must be even... COG=3 handled below)
    extern __shared__ char smraw[];
    pk_t* swgt = (pk_t*)smraw;   // [ci][t9][kz3][co] duplicated (w,w)

    int bz = blockIdx.z;
    int zc = bz % NZCc; bz /= NZCc;
    int cg = bz % NCG;  bz /= NCG;
    int b  = bz;
    int co0 = cg * COG;

    int tid = threadIdx.y * 8 + threadIdx.x;
    constexpr int COGP = (COG & 1) ? COG + 1 : COG;   // pad odd COG for alignment
    for (int i = tid; i < CTOT * 27 * COGP; i += 256) {
        int co = i % COGP;
        int r  = i / COGP;
        int kz = r % 3;
        int t  = (r / 3) % 9;
        int ci = r / 27;
        int cog = co0 + co;
        float wv = (co < COG && cog < COUT_STORE)
            ? __ldg(w + ((size_t)cog * CTOT + ci) * 27 + kz * 9 + t) : 0.f;
        swgt[i] = pack2(wv, wv);
    }
    __syncthreads();

    int gx = blockIdx.x * 32 + threadIdx.x * 4;
    int y  = blockIdx.y * 32 + threadIdx.y;
    int zs = zc * ZCc;

    const float* base0 = in0 + (size_t)b * CIN0 * VOL + y * 96 + gx;
    const float* base1 = (CIN1 > 0) ? in1 + (size_t)b * CIN1 * VOL + y * 96 + gx : nullptr;
    const float* base2 = (CIN2 > 0) ? in2 + (size_t)b * CIN2 * VOL + y * 96 + gx : nullptr;

    pk_t bpk[COG];
#pragma unroll
    for (int co = 0; co < COG; co++) {
        float bv = (co0 + co < COUT_STORE) ? __ldg(bias + co0 + co) : 0.f;
        bpk[co] = pack2(bv, bv);
    }

    pk_t a0[2 * COG], a1[2 * COG], a2[2 * COG];
#pragma unroll
    for (int i = 0; i < 2 * COG; i++) { a0[i] = 0ull; a1[i] = 0ull; a2[i] = 0ull; }

    // Apply one kz-row of COG weights (LDS.128 pairs) to both x-pairs.
#define KZROW(S, WKZ, P0, P1)                                                  \
    {                                                                          \
        _Pragma("unroll")                                                      \
        for (int h = 0; h < COGH; h++) {                                       \
            ulonglong2 wv = *(const ulonglong2*)((WKZ) + 2 * h);               \
            S[2 * h]           = ffma2(P0, wv.x, S[2 * h]);                    \
            S[COG + 2 * h]     = ffma2(P1, wv.x, S[COG + 2 * h]);              \
            S[2 * h + 1]       = ffma2(P0, wv.y, S[2 * h + 1]);                \
            S[COG + 2 * h + 1] = ffma2(P1, wv.y, S[COG + 2 * h + 1]);          \
        }                                                                      \
        if (COG & 1) {                                                         \
            pk_t wv = (WKZ)[COG - 1];                                          \
            S[COG - 1]     = ffma2(P0, wv, S[COG - 1]);                        \
            S[2 * COG - 1] = ffma2(P1, wv, S[2 * COG - 1]);                    \
        }                                                                      \
    }

    // Process one ci-segment's plane rows into AN/AC/AP (kz=0/1/2).
#define SEG_LOOP(BASE, CINSEG, CIOFF, AP, AC, AN)                              \
    _Pragma("unroll 1")                                                        \
    for (int ci = 0; ci < (CINSEG); ci++) {                                    \
        const float* p = (BASE) + ((size_t)ci) * VOL + (size_t)z * PLN;        \
        const pk_t* wci = swgt + (size_t)((CIOFF) + ci) * 27 * COGP;           \
        _Pragma("unroll")                                                      \
        for (int dy = 0; dy < 3; dy++) {                                       \
            int yy = y + dy - 1;                                               \
            bool vy = (yy >= 0 && yy <= 95);                                   \
            const float* pr = p + (dy - 1) * 96;                               \
            float4 A = make_float4(0.f, 0.f, 0.f, 0.f);                        \
            float vl = 0.f, vr = 0.f;                                          \
            if (vy) {                                                          \
                A = __ldg((const float4*)pr);                                  \
                if (gx > 0)  vl = __ldg(pr - 1);                               \
                if (gx < 92) vr = __ldg(pr + 4);                               \
            }                                                                  \
            pk_t e0 = pack2(A.x, A.y), e1 = pack2(A.z, A.w);                   \
            pk_t s0 = pack2(vl, A.x);                                          \
            pk_t s1 = pack2(A.y, A.z);                                         \
            pk_t s2 = pack2(A.w, vr);                                          \
            _Pragma("unroll")                                                  \
            for (int kx = 0; kx < 3; kx++) {                                   \
                pk_t P0 = (kx == 0) ? s0 : (kx == 1) ? e0 : s1;                \
                pk_t P1 = (kx == 0) ? s1 : (kx == 1) ? e1 : s2;                \
                const pk_t* wt = wci + ((dy * 3 + kx) * 3) * COGP;             \
                KZROW(AN, wt,            P0, P1);                              \
                KZROW(AC, wt + COGP,     P0, P1);                              \
                KZROW(AP, wt + 2 * COGP, P0, P1);                              \
            }                                                                  \
        }                                                                      \
    }

#define CONV_STEP(ZP, AP, AC, AN)                                              \
    {                                                                          \
        int z = (ZP);                                                          \
        if (z >= 0 && z <= 95 && z <= zs + ZCc) {                              \
            SEG_LOOP(base0, CIN0, 0, AP, AC, AN);                              \
            if (CIN1 > 0) { SEG_LOOP(base1, CIN1, CIN0, AP, AC, AN); }         \
            if (CIN2 > 0) { SEG_LOOP(base2, CIN2, CIN0 + CIN1, AP, AC, AN); }  \
        }                                                                      \
        int zo = z - 1;                                                        \
        if (zo >= zs && zo < zs + ZCc) {                                       \
            _Pragma("unroll")                                                  \
            for (int co = 0; co < COG; co++) {                                 \
                if (co0 + co < COUT_STORE) {                                   \
                    size_t off = ((size_t)(b * COUT_STORE + co0 + co)) * VOL + \
                                 (size_t)zo * PLN + y * 96 + gx;               \
                    float o0, o1, o2, o3, blo, bhi;                            \
                    unpack2(bpk[co], blo, bhi);                                \
                    unpack2(AP[co], o0, o1);                                   \
                    unpack2(AP[COG + co], o2, o3);                             \
                    o0 = lrelu(o0 + blo); o1 = lrelu(o1 + bhi);                \
                    o2 = lrelu(o2 + blo); o3 = lrelu(o3 + bhi);                \
                    if (RES) {                                                 \
                        float4 r4 = __ldg((const float4*)(res + off));         \
                        o0 += r4.x; o1 += r4.y; o2 += r4.z; o3 += r4.w;        \
                    }                                                          \
                    *(float4*)(out + off) = make_float4(o0, o1, o2, o3);       \
                }                                                              \
            }                                                                  \
        }                                                                      \
        _Pragma("unroll")                                                      \
        for (int i = 0; i < 2 * COG; i++) AP[i] = 0ull;                        \
    }

    for (int zb = zs - 1; zb <= zs + ZCc; zb += 3) {
        CONV_STEP(zb,     a0, a1, a2);
        CONV_STEP(zb + 1, a1, a2, a0);
        CONV_STEP(zb + 2, a2, a0, a1);
    }
#undef CONV_STEP
#undef SEG_LOOP
#undef KZROW
}

// ---------------------------------------------------------------------------
extern "C" void kernel_launch(void* const* d_in, const int* in_sizes, int n_in,
                              void* d_out, int out_size)
{
    const float* src = (const float*)d_in[0];
    const float* tgt = (const float*)d_in[1];
    const float* dvf = (const float*)d_in[2];
    const float* w1  = (const float*)d_in[3];
    const float* b1  = (const float*)d_in[4];
    const float* w2  = (const float*)d_in[5];
    const float* b2  = (const float*)d_in[6];
    const float* w3  = (const float*)d_in[7];
    const float* b3  = (const float*)d_in[8];
    float* out = (float*)d_out;

    float* warped = nullptr;
    float* corr   = nullptr;
    float* facc   = nullptr;
    cudaGetSymbolAddress((void**)&warped, g_warped);
    cudaGetSymbolAddress((void**)&corr, g_corr);
    cudaGetSymbolAddress((void**)&facc, g_facc);

    const int sm1 = 59 * 27 * 4 * (int)sizeof(pk_t);   // 50976
    const int sm2 = 16 * 27 * 4 * (int)sizeof(pk_t);   // 13824
    const int sm3 = 16 * 27 * 4 * (int)sizeof(pk_t);   // COGP=4 for COG=3

    cudaFuncSetAttribute((const void*)&convp_kernel<16, 27, 16, 16, 4, 16, 24, false>,
                         cudaFuncAttributeMaxDynamicSharedMemorySize, sm1);
    cudaFuncSetAttribute((const void*)&convp_kernel<16, 0, 0, 16, 4, 16, 24, true>,
                         cudaFuncAttributeMaxDynamicSharedMemorySize, sm2);
    cudaFuncSetAttribute((const void*)&convp_kernel<16, 0, 0, 3, 3, 3, 6, false>,
                         cudaFuncAttributeMaxDynamicSharedMemorySize, sm3);

    int nvox = B_ * VOL;
    warp_kernel<<<(nvox + 255) / 256, 256>>>(src, dvf);

    dim3 cblk(16, 16);
    dim3 cgrd(3, 6, 8 * B_);
    corrp_kernel<<<cgrd, cblk>>>(tgt);

    dim3 blk(8, 32);
    dim3 g1(3, 3, 4 * 4 * B_);    // ZC=24 (NZC=4) x NCG=4 x B -> 288 blocks (1 wave)
    dim3 g3(3, 3, 16 * 1 * B_);   // ZC=6  (NZC=16) x NCG=1 x B -> 288 blocks

    // conv1 fused over its 3 input segments (src, corr, tgt): 59ch -> 16ch, lrelu
    convp_kernel<16, 27, 16, 16, 4, 16, 24, false>
        <<<g1, blk, sm1>>>(src, corr, tgt, w1, b1, facc, nullptr);
    // conv2 + residual: fsum = f + lrelu(conv(f))
    convp_kernel<16, 0, 0, 16, 4, 16, 24, true>
        <<<g1, blk, sm2>>>(facc, nullptr, nullptr, w2, b2, warped, facc);
    // conv3: 16 -> 3
    convp_kernel<16, 0, 0, 3, 3, 3, 6, false>
        <<<g3, blk, sm3>>>(warped, nullptr, nullptr, w3, b3, out, nullptr);
}

// round 14
// speedup vs baseline: 2.1260x; 1.1365x over previous
#include <cuda_runtime.h>

#define LEAK 0.2f
constexpr int B_  = 2;
constexpr int C_  = 16;
constexpr int VOL = 96 * 96 * 96;
constexpr int PLN = 96 * 96;
constexpr int DVF = 48;

typedef unsigned long long pk_t;

// Scratch (device globals per harness rules).
__device__ float g_warped[(size_t)B_ * C_ * VOL];  // warped src; later fsum
__device__ float g_corr[(size_t)B_ * 27 * VOL];    // cost volume
__device__ float g_facc[(size_t)B_ * C_ * VOL];    // conv1 out (f)

__device__ __forceinline__ float lrelu(float v) { return v > 0.f ? v : LEAK * v; }

__device__ __forceinline__ pk_t pack2(float lo, float hi) {
    pk_t r; asm("mov.b64 %0, {%1,%2};" : "=l"(r) : "f"(lo), "f"(hi)); return r;
}
__device__ __forceinline__ void unpack2(pk_t p, float& lo, float& hi) {
    asm("mov.b64 {%0,%1}, %2;" : "=f"(lo), "=f"(hi) : "l"(p));
}
__device__ __forceinline__ pk_t ffma2(pk_t a, pk_t b, pk_t c) {
    pk_t d; asm("fma.rn.f32x2 %0, %1, %2, %3;" : "=l"(d) : "l"(a), "l"(b), "l"(c));
    return d;
}
__device__ __forceinline__ float fsel(bool p, float v) { return p ? v : 0.f; }

// ---------------------------------------------------------------------------
// K1: trilinear upsample of dvf (48^3 -> 96^3, align_corners) + warp source
// ---------------------------------------------------------------------------
__global__ void warp_kernel(const float* __restrict__ src,
                            const float* __restrict__ dvf)
{
    int idx = blockIdx.x * blockDim.x + threadIdx.x;
    if (idx >= B_ * VOL) return;
    int b = idx / VOL;
    int r = idx - b * VOL;
    int z = r / PLN;
    int y = (r / 96) % 96;
    int x = r % 96;

    const float sc = 47.0f / 95.0f;
    float pz = z * sc, py = y * sc, px = x * sc;
    int z0 = (int)pz, y0 = (int)py, x0 = (int)px;
    int z1 = min(z0 + 1, DVF - 1), y1 = min(y0 + 1, DVF - 1), x1 = min(x0 + 1, DVF - 1);
    float wz = pz - (float)z0, wy = py - (float)y0, wx = px - (float)x0;

    const float* dv = dvf + (size_t)b * 3 * DVF * DVF * DVF;
    float flow[3];
#pragma unroll
    for (int cc = 0; cc < 3; cc++) {
        const float* p = dv + (size_t)cc * DVF * DVF * DVF;
        float v000 = __ldg(p + (z0 * 48 + y0) * 48 + x0);
        float v001 = __ldg(p + (z0 * 48 + y0) * 48 + x1);
        float v010 = __ldg(p + (z0 * 48 + y1) * 48 + x0);
        float v011 = __ldg(p + (z0 * 48 + y1) * 48 + x1);
        float v100 = __ldg(p + (z1 * 48 + y0) * 48 + x0);
        float v101 = __ldg(p + (z1 * 48 + y0) * 48 + x1);
        float v110 = __ldg(p + (z1 * 48 + y1) * 48 + x0);
        float v111 = __ldg(p + (z1 * 48 + y1) * 48 + x1);
        float v00 = v000 * (1.f - wx) + v001 * wx;
        float v01 = v010 * (1.f - wx) + v011 * wx;
        float v10 = v100 * (1.f - wx) + v101 * wx;
        float v11 = v110 * (1.f - wx) + v111 * wx;
        float v0 = v00 * (1.f - wy) + v01 * wy;
        float v1 = v10 * (1.f - wy) + v11 * wy;
        flow[cc] = v0 * (1.f - wz) + v1 * wz;
    }

    float zc = (float)z + flow[0];
    float yc = (float)y + flow[1];
    float xc = (float)x + flow[2];
    float zf = floorf(zc), yf = floorf(yc), xf = floorf(xc);
    float fz = zc - zf, fy = yc - yf, fx = xc - xf;
    int iz0 = (int)zf, iy0 = (int)yf, ix0 = (int)xf;

    int   zi[2] = { iz0, iz0 + 1 };
    int   yi[2] = { iy0, iy0 + 1 };
    int   xi[2] = { ix0, ix0 + 1 };
    float wzv[2] = { 1.f - fz, fz };
    float wyv[2] = { 1.f - fy, fy };
    float wxv[2] = { 1.f - fx, fx };

    int   idx8[8];
    float w8[8];
    int j = 0;
#pragma unroll
    for (int a = 0; a < 2; a++)
#pragma unroll
        for (int bb = 0; bb < 2; bb++)
#pragma unroll
            for (int c2 = 0; c2 < 2; c2++) {
                int zz = zi[a], yy = yi[bb], xx = xi[c2];
                bool valid = (zz >= 0 && zz < 96 && yy >= 0 && yy < 96 &&
                              xx >= 0 && xx < 96);
                int zcl = min(max(zz, 0), 95);
                int ycl = min(max(yy, 0), 95);
                int xcl = min(max(xx, 0), 95);
                idx8[j] = (zcl * 96 + ycl) * 96 + xcl;
                w8[j] = valid ? (wzv[a] * wyv[bb] * wxv[c2]) : 0.f;
                j++;
            }

    const float* sb = src + (size_t)b * C_ * VOL;
    float* ob = g_warped + (size_t)b * C_ * VOL + r;
#pragma unroll
    for (int c = 0; c < C_; c++) {
        const float* sp = sb + (size_t)c * VOL;
        float v = 0.f;
#pragma unroll
        for (int k = 0; k < 8; k++) v = fmaf(w8[k], __ldg(sp + idx8[k]), v);
        ob[(size_t)c * VOL] = v;
    }
}

// ---------------------------------------------------------------------------
// K2: 27-shift cost volume, f32x2 packed, 2 x per thread, branchless inner.
// ---------------------------------------------------------------------------
__global__ void __launch_bounds__(256, 2) corrp_kernel(const float* __restrict__ tgt)
{
    constexpr int ZCC = 12, NZCC = 96 / ZCC;
    int bz = blockIdx.z;
    int zc = bz % NZCC; bz /= NZCC;
    int b = bz;
    int tx = threadIdx.x, ty = threadIdx.y;
    int gx = blockIdx.x * 32 + tx * 2;
    int y  = blockIdx.y * 16 + ty;
    int zs = zc * ZCC;

    const float* wb = g_warped + (size_t)b * C_ * VOL;
    const float* tb = tgt + (size_t)b * C_ * VOL;

    int offl = (gx > 0)  ? -1 : 0;   // loop-invariant edge offsets (in-bounds)
    int offr = (gx < 94) ?  2 : 1;   // fall back to in-row elem, selected to 0
    bool vxm = (gx > 0), vxp = (gx < 94);

    for (int z = zs; z < zs + ZCC; z++) {
        // Hoist the 9 (dz,dy) validity masks + clamped plane offsets.
        size_t soff[9];
        bool   svld[9];
#pragma unroll
        for (int dz = 0; dz < 3; dz++) {
#pragma unroll
            for (int dy = 0; dy < 3; dy++) {
                int zz = z + dz - 1, yy = y + dy - 1;
                bool v = (unsigned)zz <= 95u && (unsigned)yy <= 95u;
                int zzc = min(max(zz, 0), 95);
                int yyc = min(max(yy, 0), 95);
                soff[dz * 3 + dy] = (size_t)zzc * PLN + yyc * 96 + gx;
                svld[dz * 3 + dy] = v;
            }
        }

        pk_t acc[27];
#pragma unroll
        for (int s = 0; s < 27; s++) acc[s] = 0ull;

#pragma unroll 1
        for (int ch = 0; ch < C_; ch++) {
            pk_t t2 = *(const pk_t*)(tb + (size_t)ch * VOL + (size_t)z * PLN + y * 96 + gx);
            const float* wc = wb + (size_t)ch * VOL;
#pragma unroll
            for (int q = 0; q < 9; q++) {
                const float* pr = wc + soff[q];
                float2 m = __ldg((const float2*)pr);
                float vlr = __ldg(pr + offl);
                float vrr = __ldg(pr + offr);
                bool v = svld[q];
                float m0 = fsel(v, m.x);
                float m1 = fsel(v, m.y);
                float vl = fsel(v && vxm, vlr);
                float vr = fsel(v && vxp, vrr);
                pk_t pL = pack2(vl, m0);
                pk_t pC = pack2(m0, m1);
                pk_t pR = pack2(m1, vr);
                int s = q * 3;
                acc[s]     = ffma2(t2, pL, acc[s]);
                acc[s + 1] = ffma2(t2, pC, acc[s + 1]);
                acc[s + 2] = ffma2(t2, pR, acc[s + 2]);
            }
        }

        float* op = g_corr + (size_t)b * 27 * VOL + (size_t)z * PLN + y * 96 + gx;
#pragma unroll
        for (int s = 0; s < 27; s++) {
            float lo, hi;
            unpack2(acc[s], lo, hi);
            lo = lrelu(lo * 0.0625f);
            hi = lrelu(hi * 0.0625f);
            *(float2*)(op + (size_t)s * VOL) = make_float2(lo, hi);
        }
    }
}

// ---------------------------------------------------------------------------
// Packed 3x3x3 conv, z-ring, XPT=4 (2 packed pairs), duplicated weights in smem,
// BRANCHLESS inner loop (clamped rows + selects, hoisted masks).
// Block: (8,32) threads -> 32x32 xy tile, ZC z-chunk, COG couts.
// ---------------------------------------------------------------------------
template<int CIN0, int CIN1, int CIN2, int COUT_TOT, int COG, int COUT_STORE,
         int ZCc, bool RES>
__global__ void __launch_bounds__(256, 2) convp_kernel(
    const float* __restrict__ in0, const float* __restrict__ in1,
    const float* __restrict__ in2,
    const float* __restrict__ w, const float* __restrict__ bias,
    float* __restrict__ out, const float* __restrict__ res)
{
    constexpr int CTOT = CIN0 + CIN1 + CIN2;
    constexpr int NCG  = (COUT_TOT + COG - 1) / COG;
    constexpr int NZCc = 96 / ZCc;
    constexpr int COGP = (COG & 1) ? COG + 1 : COG;
    constexpr int COGH = COG / 2;
    extern __shared__ char smraw[];
    pk_t* swgt = (pk_t*)smraw;   // [ci][t9][kz3][COGP] duplicated (w,w)

    int bz = blockIdx.z;
    int zc = bz % NZCc; bz /= NZCc;
    int cg = bz % NCG;  bz /= NCG;
    int b  = bz;
    int co0 = cg * COG;

    int tid = threadIdx.y * 8 + threadIdx.x;
    for (int i = tid; i < CTOT * 27 * COGP; i += 256) {
        int co = i % COGP;
        int r  = i / COGP;
        int kz = r % 3;
        int t  = (r / 3) % 9;
        int ci = r / 27;
        int cog = co0 + co;
        float wv = (co < COG && cog < COUT_STORE)
            ? __ldg(w + ((size_t)cog * CTOT + ci) * 27 + kz * 9 + t) : 0.f;
        swgt[i] = pack2(wv, wv);
    }
    __syncthreads();

    int gx = blockIdx.x * 32 + threadIdx.x * 4;
    int y  = blockIdx.y * 32 + threadIdx.y;
    int zs = zc * ZCc;

    bool vxm = (gx > 0), vxp = (gx < 92);
    int offl = vxm ? -1 : 0;   // in-bounds fallback, value selected to 0
    int offr = vxp ?  4 : 3;

    // Hoisted per-thread y masks and clamped row offsets (dy = 0..2).
    bool vy[3];
    int  roff[3];
#pragma unroll
    for (int dy = 0; dy < 3; dy++) {
        int yy = y + dy - 1;
        vy[dy] = (unsigned)yy <= 95u;
        roff[dy] = min(max(yy, 0), 95) * 96 + gx;
    }

    const float* base0 = in0 + (size_t)b * CIN0 * VOL;
    const float* base1 = (CIN1 > 0) ? in1 + (size_t)b * CIN1 * VOL : nullptr;
    const float* base2 = (CIN2 > 0) ? in2 + (size_t)b * CIN2 * VOL : nullptr;

    pk_t bpk[COG];
#pragma unroll
    for (int co = 0; co < COG; co++) {
        float bv = (co0 + co < COUT_STORE) ? __ldg(bias + co0 + co) : 0.f;
        bpk[co] = pack2(bv, bv);
    }

    pk_t a0[2 * COG], a1[2 * COG], a2[2 * COG];
#pragma unroll
    for (int i = 0; i < 2 * COG; i++) { a0[i] = 0ull; a1[i] = 0ull; a2[i] = 0ull; }

#define KZROW(S, WKZ, P0, P1)                                                  \
    {                                                                          \
        _Pragma("unroll")                                                      \
        for (int h = 0; h < COGH; h++) {                                       \
            ulonglong2 wv = *(const ulonglong2*)((WKZ) + 2 * h);               \
            S[2 * h]           = ffma2(P0, wv.x, S[2 * h]);                    \
            S[COG + 2 * h]     = ffma2(P1, wv.x, S[COG + 2 * h]);              \
            S[2 * h + 1]       = ffma2(P0, wv.y, S[2 * h + 1]);                \
            S[COG + 2 * h + 1] = ffma2(P1, wv.y, S[COG + 2 * h + 1]);          \
        }                                                                      \
        if (COG & 1) {                                                         \
            pk_t wv = (WKZ)[COG - 1];                                          \
            S[COG - 1]     = ffma2(P0, wv, S[COG - 1]);                        \
            S[2 * COG - 1] = ffma2(P1, wv, S[2 * COG - 1]);                    \
        }                                                                      \
    }

#define SEG_LOOP(BASE, CINSEG, CIOFF, AP, AC, AN)                              \
    _Pragma("unroll 1")                                                        \
    for (int ci = 0; ci < (CINSEG); ci++) {                                    \
        const float* p = (BASE) + ((size_t)ci) * VOL + (size_t)z * PLN;        \
        const pk_t* wci = swgt + (size_t)((CIOFF) + ci) * 27 * COGP;           \
        _Pragma("unroll")                                                      \
        for (int dy = 0; dy < 3; dy++) {                                       \
            const float* pr = p + roff[dy];                                    \
            float4 A = __ldg((const float4*)pr);                               \
            float vlr = __ldg(pr + offl);                                      \
            float vrr = __ldg(pr + offr);                                      \
            bool v = vy[dy];                                                   \
            float ax = fsel(v, A.x), ay = fsel(v, A.y);                        \
            float az = fsel(v, A.z), aw = fsel(v, A.w);                        \
            float vl = fsel(v && vxm, vlr);                                    \
            float vr = fsel(v && vxp, vrr);                                    \
            pk_t e0 = pack2(ax, ay), e1 = pack2(az, aw);                       \
            pk_t s0 = pack2(vl, ax);                                           \
            pk_t s1 = pack2(ay, az);                                           \
            pk_t s2 = pack2(aw, vr);                                           \
            _Pragma("unroll")                                                  \
            for (int kx = 0; kx < 3; kx++) {                                   \
                pk_t P0 = (kx == 0) ? s0 : (kx == 1) ? e0 : s1;                \
                pk_t P1 = (kx == 0) ? s1 : (kx == 1) ? e1 : s2;                \
                const pk_t* wt = wci + ((dy * 3 + kx) * 3) * COGP;             \
                KZROW(AN, wt,            P0, P1);                              \
                KZROW(AC, wt + COGP,     P0, P1);                              \
                KZROW(AP, wt + 2 * COGP, P0, P1);                              \
            }                                                                  \
        }                                                                      \
    }

#define CONV_STEP(ZP, AP, AC, AN)                                              \
    {                                                                          \
        int z = (ZP);                                                          \
        if (z >= 0 && z <= 95 && z <= zs + ZCc) {                              \
            SEG_LOOP(base0, CIN0, 0, AP, AC, AN);                              \
            if (CIN1 > 0) { SEG_LOOP(base1, CIN1, CIN0, AP, AC, AN); }         \
            if (CIN2 > 0) { SEG_LOOP(base2, CIN2, CIN0 + CIN1, AP, AC, AN); }  \
        }                                                                      \
        int zo = z - 1;                                                        \
        if (zo >= zs && zo < zs + ZCc) {                                       \
            _Pragma("unroll")                                                  \
            for (int co = 0; co < COG; co++) {                                 \
                if (co0 + co < COUT_STORE) {                                   \
                    size_t off = ((size_t)(b * COUT_STORE + co0 + co)) * VOL + \
                                 (size_t)zo * PLN + y * 96 + gx;               \
                    float o0, o1, o2, o3, blo, bhi;                            \
                    unpack2(bpk[co], blo, bhi);                                \
                    unpack2(AP[co], o0, o1);                                   \
                    unpack2(AP[COG + co], o2, o3);                             \
                    o0 = lrelu(o0 + blo); o1 = lrelu(o1 + bhi);                \
                    o2 = lrelu(o2 + blo); o3 = lrelu(o3 + bhi);                \
                    if (RES) {                                                 \
                        float4 r4 = __ldg((const float4*)(res + off));         \
                        o0 += r4.x; o1 += r4.y; o2 += r4.z; o3 += r4.w;        \
                    }                                                          \
                    *(float4*)(out + off) = make_float4(o0, o1, o2, o3);       \
                }                                                              \
            }                                                                  \
        }                                                                      \
        _Pragma("unroll")                                                      \
        for (int i = 0; i < 2 * COG; i++) AP[i] = 0ull;                        \
    }

    for (int zb = zs - 1; zb <= zs + ZCc; zb += 3) {
        CONV_STEP(zb,     a0, a1, a2);
        CONV_STEP(zb + 1, a1, a2, a0);
        CONV_STEP(zb + 2, a2, a0, a1);
    }
#undef CONV_STEP
#undef SEG_LOOP
#undef KZROW
}

// ---------------------------------------------------------------------------
extern "C" void kernel_launch(void* const* d_in, const int* in_sizes, int n_in,
                              void* d_out, int out_size)
{
    const float* src = (const float*)d_in[0];
    const float* tgt = (const float*)d_in[1];
    const float* dvf = (const float*)d_in[2];
    const float* w1  = (const float*)d_in[3];
    const float* b1  = (const float*)d_in[4];
    const float* w2  = (const float*)d_in[5];
    const float* b2  = (const float*)d_in[6];
    const float* w3  = (const float*)d_in[7];
    const float* b3  = (const float*)d_in[8];
    float* out = (float*)d_out;

    float* warped = nullptr;
    float* corr   = nullptr;
    float* facc   = nullptr;
    cudaGetSymbolAddress((void**)&warped, g_warped);
    cudaGetSymbolAddress((void**)&corr, g_corr);
    cudaGetSymbolAddress((void**)&facc, g_facc);

    const int sm1 = 59 * 27 * 4 * (int)sizeof(pk_t);   // 50976
    const int sm2 = 16 * 27 * 4 * (int)sizeof(pk_t);   // 13824
    const int sm3 = 16 * 27 * 4 * (int)sizeof(pk_t);   // COGP=4 for COG=3

    cudaFuncSetAttribute((const void*)&convp_kernel<16, 27, 16, 16, 4, 16, 24, false>,
                         cudaFuncAttributeMaxDynamicSharedMemorySize, sm1);
    cudaFuncSetAttribute((const void*)&convp_kernel<16, 0, 0, 16, 4, 16, 24, true>,
                         cudaFuncAttributeMaxDynamicSharedMemorySize, sm2);
    cudaFuncSetAttribute((const void*)&convp_kernel<16, 0, 0, 3, 3, 3, 6, false>,
                         cudaFuncAttributeMaxDynamicSharedMemorySize, sm3);

    int nvox = B_ * VOL;
    warp_kernel<<<(nvox + 255) / 256, 256>>>(src, dvf);

    dim3 cblk(16, 16);
    dim3 cgrd(3, 6, 8 * B_);
    corrp_kernel<<<cgrd, cblk>>>(tgt);

    dim3 blk(8, 32);
    dim3 g1(3, 3, 4 * 4 * B_);    // ZC=24 (NZC=4) x NCG=4 x B -> 288 blocks (1 wave)
    dim3 g3(3, 3, 16 * 1 * B_);   // ZC=6  (NZC=16) x NCG=1 x B -> 288 blocks

    // conv1 fused over its 3 input segments (src, corr, tgt): 59ch -> 16ch, lrelu
    convp_kernel<16, 27, 16, 16, 4, 16, 24, false>
        <<<g1, blk, sm1>>>(src, corr, tgt, w1, b1, facc, nullptr);
    // conv2 + residual: fsum = f + lrelu(conv(f))
    convp_kernel<16, 0, 0, 16, 4, 16, 24, true>
        <<<g1, blk, sm2>>>(facc, nullptr, nullptr, w2, b2, warped, facc);
    // conv3: 16 -> 3
    convp_kernel<16, 0, 0, 3, 3, 3, 6, false>
        <<<g3, blk, sm3>>>(warped, nullptr, nullptr, w3, b3, out, nullptr);
}